// round 7
// baseline (speedup 1.0000x reference)
#include <cuda_runtime.h>

// ---------------------------------------------------------------------------
// R7: integer closed-form digit extraction.
//
// Semantics identical to R6 (passed, rel_err 3.3e-6):
//  * value = |mem[b, addr[b]]| exactly (eq_gate is an exact one-hot).
//  * v < 2^24, so u = (int)v is exact floor(v), and for d = 10^p (integer):
//      floor(v/d) == floor(u/d)  exactly.
//    => chained integer /10 ladder replaces all float quotient machinery.
//  * count: n = 1 + #{i in 1..5 : u >= 10^i}  (== v >= 10^i for v >= 0).
//  * qmax clipping per pos (reference loop break): {999,101,11,2,1,1}.
//  * rare cutoff bands (quot = qmax*st near v = (qmax+1)*d - 0.5) and the
//    v < 1001 soft pos-0 sum are kept verbatim from R6 (warp-uniform, ~1%).
// ---------------------------------------------------------------------------

static __device__ __forceinline__ float sigm(float z) {
    return __fdividef(1.0f, 1.0f + __expf(-z));
}
// silu_threshold(x) = (silu(20x+10) - silu(20x-10)) / 20
static __device__ __forceinline__ float st_fast(float x) {
    float z1 = __fmaf_rn(20.0f, x, 10.0f);
    float z2 = __fmaf_rn(20.0f, x, -10.0f);
    return (z1 * sigm(z1) - z2 * sigm(z2)) * 0.05f;
}
// reference digit = floor(quot - floor(quot/10)*10); handles negative quot.
static __device__ __forceinline__ int mod10_digit(float quot) {
    return (int)floorf(quot - floorf(quot * 0.1f) * 10.0f);
}

__global__ void __launch_bounds__(128)
c4_printf_warp_kernel(const float* __restrict__ mem,
                      const int*   __restrict__ addr,
                      const int*   __restrict__ outp,
                      float*       __restrict__ out,
                      int B, int M) {
    const unsigned FULL = 0xFFFFFFFFu;
    int warp = (blockIdx.x * blockDim.x + threadIdx.x) >> 5;
    int lane = threadIdx.x & 31;
    if (warp >= B) return;
    const int b = warp;

    // Warp-uniform loads (single sector, L1 broadcast).
    int   a  = __ldg(addr + b);
    int   op = __ldg(outp + b);
    float v  = fabsf(__ldg(mem + b * M + a));

    // --- integer digit ladder -------------------------------------------------
    int u  = (int)v;          // exact floor, v < 2^24
    int q1 = u  / 10;
    int q2 = q1 / 10;
    int q3 = q2 / 10;
    int q4 = q3 / 10;
    int q5 = q4 / 10;
    int q6 = q5 / 10;

    int d1 = (q1 <= 101) ? (q1 - 10 * q2) : 0;
    int d2 = (q2 <= 11)  ? (q2 - 10 * q3) : 0;
    int d3 = (q3 <= 2)   ? (q3 - 10 * q4) : 0;
    int d4 = (q4 <= 1)   ? (q4 - 10 * q5) : 0;
    int d5 = (q5 <= 1)   ? (q5 - 10 * q6) : 0;

    // --- digit count: integer comparisons --------------------------------------
    int n = 1 + (u >= 10) + (u >= 100) + (u >= 1000)
              + (u >= 10000) + (u >= 100000);

    // --- qmax cutoff bands (warp-uniform, ~0.03% hit rate) ---------------------
    if (v > 1018.0f && v < 20001.0f) {
        if (fabsf(v - 1019.5f) < 1.41f) {
            float g = 1019.5f - v;
            float s = (g > -1.4011f) ? st_fast(g) : 0.0f;
            d1 = mod10_digit(101.0f * s);
        } else if (fabsf(v - 1199.5f) < 1.41f) {
            float g = 1199.5f - v;
            float s = (g > -1.4011f) ? st_fast(g) : 0.0f;
            d2 = mod10_digit(11.0f * s);
        } else if (fabsf(v - 2999.5f) < 1.41f) {
            float g = 2999.5f - v;
            float s = (g > -1.4011f) ? st_fast(g) : 0.0f;
            d3 = mod10_digit(2.0f * s);
        } else if (fabsf(v - 19999.5f) < 1.41f) {
            float g = 19999.5f - v;
            float s = (g > -1.4011f) ? st_fast(g) : 0.0f;
            d4 = mod10_digit(1.0f * s);
        }
    }

    // --- pos 0: soft 4-term sum, only when any gate is live (~1% of rows) ------
    int d0 = 0;
    if (v < 1001.0f) {
        int off = lane & 3;                       // every 4-lane group computes
        int qlo = (int)floorf(v - 1.93f) + 1;     // the same 4 live terms
        int q = qlo + off;
        float term = 0.0f;
        if (q >= 0 && q <= 999) {
            float qf = (float)q;
            float a1 = v - qf + 0.5f;             // lower gate arg (d = 1)
            float a2 = qf + 0.5f - v;             // upper gate arg
            term = st_fast(a1) * st_fast(a2) * qf;
        }
        term += __shfl_xor_sync(FULL, term, 1);   // group-of-4 reduction
        term += __shfl_xor_sync(FULL, term, 2);
        d0 = mod10_digit(term);
    }

    // --- nibble-pack digits (warp-uniform) --------------------------------------
    unsigned pack = (unsigned)d0 | ((unsigned)d1 << 4) | ((unsigned)d2 << 8)
                  | ((unsigned)d3 << 12) | ((unsigned)d4 << 16)
                  | ((unsigned)d5 << 20);

    // --- branch-free epilogue: each lane owns cols lane and lane+32 --------------
    float* orow = out + b * 65;
    int j0 = lane - op;
    int j1 = lane + 32 - op;

    int pi0 = n - 1 - j0; pi0 = pi0 < 0 ? 0 : (pi0 > 5 ? 5 : pi0);
    int pi1 = n - 1 - j1; pi1 = pi1 < 0 ? 0 : (pi1 > 5 ? 5 : pi1);
    float g0 = (float)((pack >> (pi0 * 4)) & 15u);
    float g1 = (float)((pack >> (pi1 * 4)) & 15u);

    float t0 = (j0 >= 0 && j0 < n) ? (48.0f + g0) : ((j0 == n) ? 10.0f : 0.0f);
    float t1 = (j1 >= 0 && j1 < n) ? (48.0f + g1) : ((j1 == n) ? 10.0f : 0.0f);

    orow[lane]      = t0;
    orow[lane + 32] = t1;
    if (lane == 0) orow[64] = v;   // appended value column (exact)
}

extern "C" void kernel_launch(void* const* d_in, const int* in_sizes, int n_in,
                              void* d_out, int out_size) {
    const float* mem  = (const float*)d_in[0];   // [B, M] fp32
    const int*   addr = (const int*)d_in[1];     // [B] int32
    const int*   outp = (const int*)d_in[2];     // [B] int32
    float*       out  = (float*)d_out;           // [B, 65] fp32

    int B = in_sizes[1];
    int M = in_sizes[0] / B;

    int threads = 128;   // 4 warps/block -> 2048 blocks: smoother distribution
    int blocks  = (B + (threads / 32) - 1) / (threads / 32);
    c4_printf_warp_kernel<<<blocks, threads>>>(mem, addr, outp, out, B, M);
}